// round 6
// baseline (speedup 1.0000x reference)
#include <cuda_runtime.h>

#define NN 100000
#define EE 1600000
#define HH 64
#define GG 128
#define CC 10
#define NB1 98   // ceil(NN/1024)

// ---------------- scratch (device globals: no runtime allocation) ----------------
__device__ int   g_csrc[EE];
__device__ int   g_deg[NN];
__device__ int   g_rowptr[NN];
__device__ int   g_cursor[NN];
__device__ int   g_incl[NN];
__device__ int   g_bsum[128];
__device__ float g_h1[(size_t)NN * HH];   // pre-activation features (reused both layers)
__device__ float g_hx[(size_t)NN * HH];   // post softmax+bias+elu (reused both layers)
__device__ float g_als[NN];
__device__ float g_ald[NN];
__device__ int   g_i64;

__device__ __forceinline__ float lrelu(float x) { return x > 0.f ? x : 0.2f * x; }
__device__ __forceinline__ float elu_(float x)  { return x > 0.f ? x : expm1f(x); }

// ---------------- zero + dtype detect (int64 indices have zero high words) ----------
__global__ void zero_kernel(const int* __restrict__ ei_w, float* __restrict__ out) {
    int i = blockIdx.x * blockDim.x + threadIdx.x;
    if (i == 0) {
        int flag = 1;
        for (int k = 0; k < 64; k++)
            if (ei_w[2 * k + 1] != 0) flag = 0;
        g_i64 = flag;
    }
    if (i < NN) g_deg[i] = 0;
    if (i < GG * CC) out[i] = 0.f;
}

// ---------------- degree histogram straight from input ----------------
__global__ void prep_kernel(const int* __restrict__ ei_w) {
    int i = blockIdx.x * blockDim.x + threadIdx.x;
    if (i >= EE) return;
    int d;
    if (g_i64) d = (int)((const long long*)ei_w)[EE + i];
    else       d = ei_w[EE + i];
    atomicAdd(&g_deg[d], 1);
}

// ---------------- 3-kernel exclusive scan of g_deg -> g_rowptr ----------------
__global__ void scan1_kernel() {
    __shared__ int sm[1024];
    int t = threadIdx.x;
    int i = blockIdx.x * 1024 + t;
    int v = (i < NN) ? g_deg[i] : 0;
    sm[t] = v;
    __syncthreads();
#pragma unroll
    for (int off = 1; off < 1024; off <<= 1) {
        int x = (t >= off) ? sm[t - off] : 0;
        __syncthreads();
        sm[t] += x;
        __syncthreads();
    }
    if (i < NN) g_incl[i] = sm[t];
    if (t == 1023) g_bsum[blockIdx.x] = sm[t];
}

// parallel block-sum scan (was a 13us serial single-thread loop)
__global__ void scan2_kernel() {
    __shared__ int sm[128];
    int t = threadIdx.x;
    int v = (t < NB1) ? g_bsum[t] : 0;
    sm[t] = v;
    __syncthreads();
#pragma unroll
    for (int off = 1; off < 128; off <<= 1) {
        int x = (t >= off) ? sm[t - off] : 0;
        __syncthreads();
        sm[t] += x;
        __syncthreads();
    }
    if (t < NB1) g_bsum[t] = sm[t] - v;   // exclusive
}

__global__ void scan3_kernel() {
    int i = blockIdx.x * blockDim.x + threadIdx.x;
    if (i >= NN) return;
    int excl = g_incl[i] - g_deg[i] + g_bsum[i >> 10];
    g_rowptr[i] = excl;
    g_cursor[i] = excl;
}

// ---------------- CSR fill straight from input ----------------
__global__ void fill_kernel(const int* __restrict__ ei_w) {
    int i = blockIdx.x * blockDim.x + threadIdx.x;
    if (i >= EE) return;
    int s, d;
    if (g_i64) {
        const long long* e64 = (const long long*)ei_w;
        s = (int)e64[i];
        d = (int)e64[EE + i];
    } else {
        s = ei_w[i];
        d = ei_w[EE + i];
    }
    int slot = atomicAdd(&g_cursor[d], 1);
    g_csrc[slot] = s;
}

// ---------------- GEMM (Nx64 @ 64x64) + attention-halves epilogue ----------------
// mode 0: read external x; mode 1: read g_hx
__global__ __launch_bounds__(128) void gemm_gat(
    int mode, const float* __restrict__ xext, const float* __restrict__ W,
    const float* __restrict__ avs, const float* __restrict__ avd)
{
    __shared__ float4 Ws[64 * 16];
    __shared__ float as_s[64], ad_s[64];
    int tid = threadIdx.x;
    const float4* W4 = (const float4*)W;
    for (int i = tid; i < 64 * 16; i += 128) Ws[i] = W4[i];
    if (tid < 64) { as_s[tid] = avs[tid]; ad_s[tid] = avd[tid]; }
    __syncthreads();

    int row = blockIdx.x * 128 + tid;
    if (row >= NN) return;
    size_t base = (size_t)row * HH;

    float o[64];
#pragma unroll
    for (int c = 0; c < 64; c++) o[c] = 0.f;

    const float* xin = mode ? g_hx : xext;
    const float4* xp = (const float4*)(xin + base);
#pragma unroll 4
    for (int k4 = 0; k4 < 16; k4++) {
        float4 v = xp[k4];
        float xk[4] = {v.x, v.y, v.z, v.w};
#pragma unroll
        for (int kk = 0; kk < 4; kk++) {
            int k = 4 * k4 + kk;
            float xv = xk[kk];
#pragma unroll
            for (int c4 = 0; c4 < 16; c4++) {
                float4 w = Ws[k * 16 + c4];
                o[4 * c4 + 0] = fmaf(xv, w.x, o[4 * c4 + 0]);
                o[4 * c4 + 1] = fmaf(xv, w.y, o[4 * c4 + 1]);
                o[4 * c4 + 2] = fmaf(xv, w.z, o[4 * c4 + 2]);
                o[4 * c4 + 3] = fmaf(xv, w.w, o[4 * c4 + 3]);
            }
        }
    }

    float als = 0.f, ald = 0.f;
    float4* hop = (float4*)(g_h1 + base);
#pragma unroll
    for (int c4 = 0; c4 < 16; c4++) {
        float4 v;
        v.x = o[4 * c4 + 0]; v.y = o[4 * c4 + 1];
        v.z = o[4 * c4 + 2]; v.w = o[4 * c4 + 3];
        hop[c4] = v;
        als += v.x * as_s[4 * c4 + 0] + v.y * as_s[4 * c4 + 1]
             + v.z * as_s[4 * c4 + 2] + v.w * as_s[4 * c4 + 3];
        ald += v.x * ad_s[4 * c4 + 0] + v.y * ad_s[4 * c4 + 1]
             + v.z * ad_s[4 * c4 + 2] + v.w * ad_s[4 * c4 + 3];
    }
    g_als[row] = als;
    g_ald[row] = ald;
}

// ---------------- warp-per-dst gather: softmax + weighted sum + bias + elu ----------
// Inner loops restructured: 4 (s, ex) broadcasts then 4 independent LDG.64 -> MLP=4.
__global__ __launch_bounds__(256) void gather_kernel(const float* __restrict__ bias) {
    __shared__ float bs[64];
    if (threadIdx.x < 64) bs[threadIdx.x] = bias[threadIdx.x];
    __syncthreads();

    int d = (blockIdx.x * 256 + threadIdx.x) >> 5;
    int lane = threadIdx.x & 31;
    if (d >= NN) return;

    const float* __restrict__ h = g_h1;
    const unsigned FULL = 0xffffffffu;
    float aldd = g_ald[d];
    float m_self = lrelu(g_als[d] + aldd);
    int row = g_rowptr[d];
    int deg = g_deg[d];
    size_t db = (size_t)d * HH;

    float2 hv0 = *(const float2*)(h + db + 2 * lane);
    float accx, accy, den, exs;

    if (deg <= 32) {
        // ---- fast path: one register-resident pass ----
        int   s_l = 0;
        float e_l = -1e30f;
        if (lane < deg) {
            s_l = g_csrc[row + lane];
            e_l = lrelu(g_als[s_l] + aldd);
        }
        float m = fmaxf(m_self, e_l);
#pragma unroll
        for (int off = 16; off; off >>= 1) m = fmaxf(m, __shfl_xor_sync(FULL, m, off));
        float ex_l = (lane < deg) ? __expf(e_l - m) : 0.f;
        den = ex_l;
        exs = __expf(m_self - m);
        accx = exs * hv0.x;
        accy = exs * hv0.y;
        int k = 0;
        for (; k + 4 <= deg; k += 4) {
            int   s0 = __shfl_sync(FULL, s_l, k + 0);
            int   s1 = __shfl_sync(FULL, s_l, k + 1);
            int   s2 = __shfl_sync(FULL, s_l, k + 2);
            int   s3 = __shfl_sync(FULL, s_l, k + 3);
            float x0 = __shfl_sync(FULL, ex_l, k + 0);
            float x1 = __shfl_sync(FULL, ex_l, k + 1);
            float x2 = __shfl_sync(FULL, ex_l, k + 2);
            float x3 = __shfl_sync(FULL, ex_l, k + 3);
            float2 v0 = *(const float2*)(h + (size_t)s0 * HH + 2 * lane);
            float2 v1 = *(const float2*)(h + (size_t)s1 * HH + 2 * lane);
            float2 v2 = *(const float2*)(h + (size_t)s2 * HH + 2 * lane);
            float2 v3 = *(const float2*)(h + (size_t)s3 * HH + 2 * lane);
            accx = fmaf(x0, v0.x, accx); accy = fmaf(x0, v0.y, accy);
            accx = fmaf(x1, v1.x, accx); accy = fmaf(x1, v1.y, accy);
            accx = fmaf(x2, v2.x, accx); accy = fmaf(x2, v2.y, accy);
            accx = fmaf(x3, v3.x, accx); accy = fmaf(x3, v3.y, accy);
        }
        for (; k < deg; k++) {
            float ex = __shfl_sync(FULL, ex_l, k);
            int   s  = __shfl_sync(FULL, s_l, k);
            float2 hv = *(const float2*)(h + (size_t)s * HH + 2 * lane);
            accx = fmaf(ex, hv.x, accx);
            accy = fmaf(ex, hv.y, accy);
        }
    } else {
        // ---- general two-pass path (rare for Poisson(16) degrees) ----
        float m = m_self;
        for (int j = lane; j < deg; j += 32) {
            int s = g_csrc[row + j];
            m = fmaxf(m, lrelu(g_als[s] + aldd));
        }
#pragma unroll
        for (int off = 16; off; off >>= 1) m = fmaxf(m, __shfl_xor_sync(FULL, m, off));
        exs = __expf(m_self - m);
        accx = exs * hv0.x;
        accy = exs * hv0.y;
        den = 0.f;
        for (int base = 0; base < deg; base += 32) {
            int jl = base + lane;
            int s_l = 0; float ex_l = 0.f;
            if (jl < deg) {
                s_l = g_csrc[row + jl];
                ex_l = __expf(lrelu(g_als[s_l] + aldd) - m);
            }
            den += ex_l;
            int cnt = deg - base; if (cnt > 32) cnt = 32;
            int k = 0;
            for (; k + 4 <= cnt; k += 4) {
                int   s0 = __shfl_sync(FULL, s_l, k + 0);
                int   s1 = __shfl_sync(FULL, s_l, k + 1);
                int   s2 = __shfl_sync(FULL, s_l, k + 2);
                int   s3 = __shfl_sync(FULL, s_l, k + 3);
                float x0 = __shfl_sync(FULL, ex_l, k + 0);
                float x1 = __shfl_sync(FULL, ex_l, k + 1);
                float x2 = __shfl_sync(FULL, ex_l, k + 2);
                float x3 = __shfl_sync(FULL, ex_l, k + 3);
                float2 v0 = *(const float2*)(h + (size_t)s0 * HH + 2 * lane);
                float2 v1 = *(const float2*)(h + (size_t)s1 * HH + 2 * lane);
                float2 v2 = *(const float2*)(h + (size_t)s2 * HH + 2 * lane);
                float2 v3 = *(const float2*)(h + (size_t)s3 * HH + 2 * lane);
                accx = fmaf(x0, v0.x, accx); accy = fmaf(x0, v0.y, accy);
                accx = fmaf(x1, v1.x, accx); accy = fmaf(x1, v1.y, accy);
                accx = fmaf(x2, v2.x, accx); accy = fmaf(x2, v2.y, accy);
                accx = fmaf(x3, v3.x, accx); accy = fmaf(x3, v3.y, accy);
            }
            for (; k < cnt; k++) {
                float ex = __shfl_sync(FULL, ex_l, k);
                int   s  = __shfl_sync(FULL, s_l, k);
                float2 hv = *(const float2*)(h + (size_t)s * HH + 2 * lane);
                accx = fmaf(ex, hv.x, accx);
                accy = fmaf(ex, hv.y, accy);
            }
        }
    }
#pragma unroll
    for (int off = 16; off; off >>= 1) den += __shfl_xor_sync(FULL, den, off);
    den += exs;   // self-loop term (warp-uniform)
    float inv = 1.f / den;
    float2 o;
    o.x = elu_(accx * inv + bs[2 * lane + 0]);
    o.y = elu_(accy * inv + bs[2 * lane + 1]);
    *(float2*)(g_hx + db + 2 * lane) = o;
}

// ---------------- MLP head + pooled output ----------------
__global__ __launch_bounds__(128) void final_kernel(
    const float* __restrict__ mw1, const float* __restrict__ mb1,
    const float* __restrict__ mw2, const float* __restrict__ mb2,
    const void* __restrict__ batch, float* __restrict__ out)
{
    __shared__ float mw1T[64 * 64];
    __shared__ float mw2s[64 * CC];
    __shared__ float mb1s[64], mb2s[CC];
    int tid = threadIdx.x;
    for (int i = tid; i < 64 * 64; i += 128) {
        int c = i >> 6, j = i & 63;
        mw1T[j * 64 + c] = mw1[i];
    }
    for (int i = tid; i < 64 * CC; i += 128) mw2s[i] = mw2[i];
    if (tid < 64) mb1s[tid] = mb1[tid];
    if (tid < CC) mb2s[tid] = mb2[tid];
    __syncthreads();

    int row = blockIdx.x * 128 + tid;
    int lane = tid & 31;
    bool active = row < NN;

    float o[CC];
#pragma unroll
    for (int c = 0; c < CC; c++) o[c] = 0.f;
    int g = 0;

    if (active) {
        size_t base = (size_t)row * HH;
        float hf[64];
        const float4* hp = (const float4*)(g_hx + base);
#pragma unroll
        for (int i = 0; i < 16; i++) {
            float4 h = hp[i];
            hf[4 * i + 0] = h.x; hf[4 * i + 1] = h.y;
            hf[4 * i + 2] = h.z; hf[4 * i + 3] = h.w;
        }
#pragma unroll
        for (int c = 0; c < CC; c++) o[c] = mb2s[c];
        const float4* m1 = (const float4*)mw1T;
#pragma unroll 4
        for (int j = 0; j < 64; j++) {
            float t = mb1s[j];
#pragma unroll
            for (int c4 = 0; c4 < 16; c4++) {
                float4 w = m1[j * 16 + c4];
                t = fmaf(hf[4 * c4 + 0], w.x, t);
                t = fmaf(hf[4 * c4 + 1], w.y, t);
                t = fmaf(hf[4 * c4 + 2], w.z, t);
                t = fmaf(hf[4 * c4 + 3], w.w, t);
            }
            t = fmaxf(t, 0.f);
#pragma unroll
            for (int c = 0; c < CC; c++) o[c] = fmaf(t, mw2s[j * CC + c], o[c]);
        }
        if (g_i64) g = (int)((const long long*)batch)[row];
        else       g = ((const int*)batch)[row];
    }

    // batch is sorted -> most warps are graph-uniform: reduce in-warp, 1 atomic/col
    unsigned mask = 0xffffffffu;
    int g0 = __shfl_sync(mask, g, 0);
    bool uni = __all_sync(mask, g == g0);
    if (uni) {
#pragma unroll
        for (int c = 0; c < CC; c++) {
            float v = o[c];
#pragma unroll
            for (int off = 16; off > 0; off >>= 1) v += __shfl_xor_sync(mask, v, off);
            if (lane == 0) atomicAdd(&out[g0 * CC + c], v);
        }
    } else {
        if (active) {
#pragma unroll
            for (int c = 0; c < CC; c++) atomicAdd(&out[g * CC + c], o[c]);
        }
    }
}

// ---------------- launch ----------------
extern "C" void kernel_launch(void* const* d_in, const int* in_sizes, int n_in,
                              void* d_out, int out_size) {
    const float* x     = (const float*)d_in[0];
    const int*   ei_w  = (const int*)d_in[1];
    const void*  batch = d_in[2];
    const float* W1  = (const float*)d_in[3];
    const float* as1 = (const float*)d_in[4];
    const float* ad1 = (const float*)d_in[5];
    const float* b1  = (const float*)d_in[6];
    const float* W2  = (const float*)d_in[7];
    const float* as2 = (const float*)d_in[8];
    const float* ad2 = (const float*)d_in[9];
    const float* b2  = (const float*)d_in[10];
    const float* mw1 = (const float*)d_in[11];
    const float* mb1 = (const float*)d_in[12];
    const float* mw2 = (const float*)d_in[13];
    const float* mb2 = (const float*)d_in[14];
    float* out = (float*)d_out;

    int gb = (NN + 127) / 128;
    int nb = (NN + 255) / 256;
    int eb = (EE + 255) / 256;
    int wb = ((NN * 32) + 255) / 256;

    zero_kernel<<<nb, 256>>>(ei_w, out);
    prep_kernel<<<eb, 256>>>(ei_w);
    scan1_kernel<<<NB1, 1024>>>();
    scan2_kernel<<<1, 128>>>();
    scan3_kernel<<<nb, 256>>>();
    fill_kernel<<<eb, 256>>>(ei_w);

    gemm_gat<<<gb, 128>>>(0, x, W1, as1, ad1);
    gather_kernel<<<wb, 256>>>(b1);

    gemm_gat<<<gb, 128>>>(1, x, W2, as2, ad2);
    gather_kernel<<<wb, 256>>>(b2);

    final_kernel<<<gb, 128>>>(mw1, mb1, mw2, mb2, batch, out);
}